// round 15
// baseline (speedup 1.0000x reference)
#include <cuda_runtime.h>
#include <cuda_fp16.h>
#include <cstdint>

#define BB 8
#define HWN 65536
#define NCHUNK 128
#define PART_STRIDE 1296

typedef uint32_t u32;

// ================= device scratch =================
// NHWC fp16 planes: [cg(0:x,1:bridge)][b][pixel][64ch]
__device__ __align__(16) __half g_in[(size_t)2 * 8 * HWN * 64];
#define PLANE(cg, b) (((size_t)((cg) * 8 + (b))) << 22)
__device__ __align__(16) __half g_Uh[(size_t)BB * HWN * 16];
__device__ __align__(16) float g_part[BB * NCHUNK * PART_STRIDE];
__device__ __align__(16) float g_PF2[BB * 16 * 64];
__device__ __align__(16) unsigned char g_Wc1[36864];
// conv2 x-weights fp16: [tap][64oc][64ic] = 73728 B
__device__ __align__(16) unsigned char g_Wc2[73728];
// conv2 U-weights fp16 per batch: [b][tap][64oc][16s]
__device__ __align__(16) __half g_W2[(size_t)BB * 9216];

// ================= helpers =================
__device__ __forceinline__ u32 smem_u32(const void* p) {
    u32 a;
    asm("{ .reg .u64 t; cvta.to.shared.u64 t, %1; cvt.u32.u64 %0, t; }" : "=r"(a) : "l"(p));
    return a;
}
__device__ __forceinline__ void ldm4(u32* r, u32 a) {
    asm volatile("ldmatrix.sync.aligned.m8n8.x4.shared.b16 {%0,%1,%2,%3}, [%4];"
                 : "=r"(r[0]), "=r"(r[1]), "=r"(r[2]), "=r"(r[3]) : "r"(a));
}
__device__ __forceinline__ void ldm4t(u32* r, u32 a) {
    asm volatile("ldmatrix.sync.aligned.m8n8.x4.trans.shared.b16 {%0,%1,%2,%3}, [%4];"
                 : "=r"(r[0]), "=r"(r[1]), "=r"(r[2]), "=r"(r[3]) : "r"(a));
}
__device__ __forceinline__ void mma16816(float* c, const u32* a, const u32* b) {
    asm volatile("mma.sync.aligned.m16n8k16.row.col.f32.f16.f16.f32 "
                 "{%0,%1,%2,%3}, {%4,%5,%6,%7}, {%8,%9}, {%0,%1,%2,%3};"
                 : "+f"(c[0]), "+f"(c[1]), "+f"(c[2]), "+f"(c[3])
                 : "r"(a[0]), "r"(a[1]), "r"(a[2]), "r"(a[3]), "r"(b[0]), "r"(b[1]));
}
__device__ __forceinline__ void cpa16(u32 dst, const void* src, bool pred) {
    unsigned sz = pred ? 16u : 0u;
    asm volatile("cp.async.cg.shared.global [%0], [%1], 16, %2;"
                 :: "r"(dst), "l"(__cvta_generic_to_global(src)), "r"(sz));
}
#define CP_COMMIT() asm volatile("cp.async.commit_group;" ::: "memory")
#define CP_WAIT0()  asm volatile("cp.async.wait_group 0;" ::: "memory")

// ================= weight prep (single fp16) =================
__global__ void prep_w_kernel(const float* __restrict__ Ws, const float* __restrict__ Wc) {
    int id = blockIdx.x * 256 + threadIdx.x;
    if (id < 64 * 1152) {
        int oc = id / 1152, rem = id - oc * 1152, ic = rem / 9, tap = rem - ic * 9;
        if (ic < 64) {
            u32 off = (u32)(tap * 8192 + oc * 128) +
                      (u32)((ic * 2) ^ ((oc & 7) << 4));
            *(__half*)(g_Wc2 + off) = __float2half(Wc[id]);
        }
    }
    if (id < 16 * 1152) {
        int oc = id / 1152, rem = id - oc * 1152, ic = rem / 9, tap = rem - ic * 9;
        u32 off = (u32)((tap * 16 + oc) * 256) + (u32)((ic * 2) ^ ((oc & 7) << 4));
        *(__half*)(g_Wc1 + off) = __float2half(Ws[id]);
    }
}

// ================= NCHW fp32 -> NHWC fp16 =================
__global__ __launch_bounds__(256)
void convert_kernel(const float* __restrict__ x, const float* __restrict__ bridge) {
    __shared__ float sT[64][68];
    int b = blockIdx.z, cg = blockIdx.y, pb = blockIdx.x;
    const float* src = cg ? bridge : x;
    int tid = threadIdx.x;
    int p0 = pb * 64;
    for (int i = tid; i < 64 * 64; i += 256) {
        int c = i >> 6, px = i & 63;
        sT[c][px] = src[((size_t)(b * 64 + c) << 16) + p0 + px];
    }
    __syncthreads();
    for (int i = tid; i < 512; i += 256) {
        int px = i >> 3, c8 = i & 7;
        __half hb[8];
#pragma unroll
        for (int j = 0; j < 8; j++)
            hb[j] = __float2half(sT[c8 * 8 + j][px]);
        size_t base = ((size_t)(p0 + px) << 6) + c8 * 8;
        *(uint4*)&g_in[PLANE(cg, b) + base] = *(uint4*)hb;
    }
}

// ================= conv1 (unchanged from R14) =================
#define C1_SLOT0 36864
#define C1_SLOTSZ 16896

__device__ __forceinline__ void c1_stage(u32 sb, int b, int x0, int ys, u32 slot, int tid) {
    bool yok = (unsigned)ys < 256u;
    int ysc = yok ? ys : 0;
    for (int i = tid; i < 1056; i += 128) {
        int p = i / 528, j = i - p * 528;
        int px = j >> 3, c8 = j & 7;
        int gx = x0 - 1 + px;
        bool ok = yok && (unsigned)gx < 256u;
        int gxc = ((unsigned)gx < 256u) ? gx : 0;
        const void* src = &g_in[PLANE(p, b) +
                                (((size_t)(ysc * 256 + gxc)) << 6) + c8 * 8];
        u32 dst = sb + slot + (u32)(p * 8448 + px * 128) +
                  (u32)((c8 * 16) ^ ((px & 7) << 4));
        cpa16(dst, src, ok);
    }
}

__global__ __launch_bounds__(128)
void conv1_kernel() {
    extern __shared__ __align__(16) unsigned char sm[];
    u32 sb = smem_u32(sm);
    int tid = threadIdx.x, lane = tid & 31, wid = tid >> 5;
    int b = blockIdx.z, y0 = blockIdx.y * 16, x0 = blockIdx.x * 64;

    for (int i = tid; i < 36864 / 16; i += 128)
        ((uint4*)sm)[i] = ((const uint4*)g_Wc1)[i];

    int i8 = lane & 7, a_mh = (lane >> 3) & 1, a_kh = lane >> 4;
    int b_kh = (lane >> 3) & 1, b_nh = lane >> 4;
    int wm = wid;
    int apx = wm * 16 + a_mh * 8 + i8;
    int ocw = b_nh * 8 + i8;
    u32 bRow = (u32)(ocw * 256), bx = (u32)((ocw & 7) << 4);
    int g = lane >> 2, t4 = lane & 3;

    c1_stage(sb, b, x0, y0 - 1, C1_SLOT0 + 3u * C1_SLOTSZ, tid);
    c1_stage(sb, b, x0, y0 + 0, C1_SLOT0 + 0u * C1_SLOTSZ, tid);
    c1_stage(sb, b, x0, y0 + 1, C1_SLOT0 + 1u * C1_SLOTSZ, tid);
    c1_stage(sb, b, x0, y0 + 2, C1_SLOT0 + 2u * C1_SLOTSZ, tid);
    CP_COMMIT();
    CP_WAIT0();
    __syncthreads();

    for (int t = 0; t < 8; t++) {
        float acc[2][2][4];
#pragma unroll
        for (int r = 0; r < 2; r++)
#pragma unroll
            for (int j = 0; j < 2; j++)
#pragma unroll
                for (int q = 0; q < 4; q++) acc[r][j][q] = 0.f;

#pragma unroll
        for (int ky = 0; ky < 3; ky++) {
            u32 sl0 = sb + C1_SLOT0 + (u32)(((2 * t + ky - 1) & 3)) * C1_SLOTSZ;
            u32 sl1 = sb + C1_SLOT0 + (u32)(((2 * t + ky) & 3)) * C1_SLOTSZ;
#pragma unroll
            for (int kx = 0; kx < 3; kx++) {
                int tap = ky * 3 + kx;
                int p = apx + kx;
                u32 aoff = (u32)(p * 128);
                u32 asw = (u32)((p & 7) << 4);
#pragma unroll
                for (int cg = 0; cg < 2; cg++) {
#pragma unroll
                    for (int kc = 0; kc < 4; kc++) {
                        u32 kb = ((u32)(kc * 32 + a_kh * 16)) ^ asw;
                        u32 Ah0[4], Ah1[4];
                        ldm4(Ah0, sl0 + (u32)(cg * 8448) + aoff + kb);
                        ldm4(Ah1, sl1 + (u32)(cg * 8448) + aoff + kb);
                        u32 ba = sb + (u32)(tap * 4096) + bRow +
                                 (((u32)(cg * 128 + kc * 32 + b_kh * 16)) ^ bx);
                        u32 BH[4];
                        ldm4(BH, ba);
#pragma unroll
                        for (int j = 0; j < 2; j++) {
                            mma16816(acc[0][j], Ah0, BH + 2 * j);
                            mma16816(acc[1][j], Ah1, BH + 2 * j);
                        }
                    }
                }
            }
        }
#pragma unroll
        for (int r = 0; r < 2; r++) {
            int yy = y0 + 2 * t + r;
            int px = x0 + wm * 16 + g;
            size_t rowb = (size_t)yy * 256 + px;
#pragma unroll
            for (int j = 0; j < 2; j++) {
                int oc = j * 8 + 2 * t4;
                size_t idx = ((size_t)b * HWN + rowb) * 16 + oc;
                __half2 hh;
                hh.x = __float2half(acc[r][j][0]);
                hh.y = __float2half(acc[r][j][1]);
                *(__half2*)&g_Uh[idx] = hh;
                hh.x = __float2half(acc[r][j][2]);
                hh.y = __float2half(acc[r][j][3]);
                *(__half2*)&g_Uh[idx + 128] = hh;
            }
        }

        __syncthreads();
        if (t < 7) {
            c1_stage(sb, b, x0, y0 + 2 * t + 3,
                     C1_SLOT0 + (u32)((2 * t + 3) & 3) * C1_SLOTSZ, tid);
            c1_stage(sb, b, x0, y0 + 2 * t + 4,
                     C1_SLOT0 + (u32)((2 * t + 4) & 3) * C1_SLOTSZ, tid);
            CP_COMMIT();
            CP_WAIT0();
            __syncthreads();
        }
    }
}

// ================= reduction via mma (unchanged from R14) =================
#define RED_SM 90112

__global__ __launch_bounds__(256)
void reduce_kernel() {
    extern __shared__ __align__(16) unsigned char rsm[];
    u32 sb = smem_u32(rsm);
    int b = blockIdx.y, ch = blockIdx.x;
    int tid = threadIdx.x, lane = tid & 31, w = tid >> 5;
    int n0 = ch * 512;

    for (int i = tid; i < 1024; i += 256) {
        int px = i >> 1, hf = i & 1;
        cpa16(sb + (u32)(px * 48 + hf * 16),
              &g_Uh[((size_t)b * HWN + n0 + px) * 16 + hf * 8], true);
    }
    for (int i = tid; i < 4096; i += 256) {
        int px = i >> 3, c8 = i & 7;
        cpa16(sb + 24576 + (u32)(px * 128) + (u32)((c8 * 16) ^ ((px & 7) << 4)),
              &g_in[PLANE(1, b) + (((size_t)(n0 + px)) << 6) + c8 * 8], true);
    }
    CP_COMMIT();
    CP_WAIT0();
    __syncthreads();

    float gacc[2][4];
    float Gacc[8][4];
#pragma unroll
    for (int j = 0; j < 2; j++)
#pragma unroll
        for (int q = 0; q < 4; q++) gacc[j][q] = 0.f;
#pragma unroll
    for (int j = 0; j < 8; j++)
#pragma unroll
        for (int q = 0; q < 4; q++) Gacc[j][q] = 0.f;

    u32 uLane = (u32)(((lane & 7) + ((lane >> 4) << 3)) * 48 + ((lane >> 3) & 1) * 16);
    u32 bLaneRow = (u32)(((lane & 7) + (((lane >> 3) & 1) << 3)) * 128);
    u32 bXor = (u32)((lane & 7) << 4);
    u32 cOff = (u32)((lane >> 4) * 16);

#pragma unroll
    for (int k = 0; k < 4; k++) {
        u32 kb = (u32)(w * 64 + k * 16);
        u32 Ar[4];
        ldm4t(Ar, sb + kb * 48 + uLane);
        u32 bg0[2] = {Ar[0], Ar[2]};
        u32 bg1[2] = {Ar[1], Ar[3]};
        mma16816(gacc[0], Ar, bg0);
        mma16816(gacc[1], Ar, bg1);
        u32 brow = sb + 24576 + kb * 128 + bLaneRow;
#pragma unroll
        for (int ng = 0; ng < 4; ng++) {
            u32 Br[4];
            ldm4t(Br, brow + (((u32)(ng * 32) + cOff) ^ bXor));
            mma16816(Gacc[2 * ng], Ar, Br);
            mma16816(Gacc[2 * ng + 1], Ar, Br + 2);
        }
    }

    float rl = 0.f;
    {
        int s = tid & 15, pb2 = (tid >> 4) * 32;
        for (int p2 = 0; p2 < 32; p2++) {
            __half u = *(const __half*)(rsm + (pb2 + p2) * 48 + s * 2);
            rl += fabsf(__half2float(u));
        }
    }
    __syncthreads();

    float* sp = (float*)rsm;
    int g = lane >> 2, t4 = lane & 3;
    int base = w * 1280;
#pragma unroll
    for (int h = 0; h < 2; h++) {
        int n = h * 8 + 2 * t4;
        sp[base + g * 16 + n] = gacc[h][0];
        sp[base + g * 16 + n + 1] = gacc[h][1];
        sp[base + (g + 8) * 16 + n] = gacc[h][2];
        sp[base + (g + 8) * 16 + n + 1] = gacc[h][3];
    }
#pragma unroll
    for (int set = 0; set < 8; set++) {
        int c = (set >> 1) * 16 + (set & 1) * 8 + 2 * t4;
        sp[base + 256 + g * 64 + c] = Gacc[set][0];
        sp[base + 256 + g * 64 + c + 1] = Gacc[set][1];
        sp[base + 256 + (g + 8) * 64 + c] = Gacc[set][2];
        sp[base + 256 + (g + 8) * 64 + c + 1] = Gacc[set][3];
    }
    sp[10240 + (tid & 15) * 16 + (tid >> 4)] = rl;
    __syncthreads();

    float* o = g_part + (size_t)(b * NCHUNK + ch) * PART_STRIDE;
    for (int i = tid; i < 1280; i += 256) {
        float a = 0.f;
#pragma unroll
        for (int w2 = 0; w2 < 8; w2++) a += sp[w2 * 1280 + i];
        o[i] = a;
    }
    if (tid < 16) {
        float a = 0.f;
#pragma unroll
        for (int j = 0; j < 16; j++) a += sp[10240 + tid * 16 + j];
        o[1280 + tid] = a;
    }
}

// ================= solve (unchanged) =================
__global__ __launch_bounds__(256)
void solve_kernel() {
    __shared__ float sGram[256];
    __shared__ float sG[1024];
    __shared__ float srr[16];
    __shared__ double A[16][17];
    __shared__ double M[16][17];
    __shared__ double spiv;
    int b = blockIdx.x;
    int tid = threadIdx.x;
    const float* base = g_part + (size_t)b * NCHUNK * PART_STRIDE;
    {
        float a = 0.f;
        for (int ch = 0; ch < NCHUNK; ch++) a += base[ch * PART_STRIDE + tid];
        sGram[tid] = a;
    }
#pragma unroll
    for (int j = 0; j < 4; j++) {
        int e = tid + j * 256;
        float a = 0.f;
        for (int ch = 0; ch < NCHUNK; ch++) a += base[ch * PART_STRIDE + 256 + e];
        sG[e] = a;
    }
    if (tid < 16) {
        float a = 0.f;
        for (int ch = 0; ch < NCHUNK; ch++) a += base[ch * PART_STRIDE + 1280 + tid];
        srr[tid] = 1e-6f + a;
    }
    __syncthreads();
    {
        int i = tid >> 4, t = tid & 15;
        A[i][t] = (double)sGram[tid] / ((double)srr[i] * (double)srr[t]);
        M[i][t] = (i == t) ? 1.0 : 0.0;
    }
    __syncthreads();
    for (int k = 0; k < 16; k++) {
        if (tid == 0) spiv = 1.0 / A[k][k];
        __syncthreads();
        if (tid < 16) { A[k][tid] *= spiv; M[k][tid] *= spiv; }
        __syncthreads();
        int i = tid >> 4, t = tid & 15;
        double f = A[i][k];
        __syncthreads();
        if (i != k) { A[i][t] -= f * A[k][t]; M[i][t] -= f * M[k][t]; }
        __syncthreads();
    }
#pragma unroll
    for (int j = 0; j < 4; j++) {
        int e = tid + j * 256;
        int s = e >> 6, c = e & 63;
        double v = 0.0;
#pragma unroll
        for (int t = 0; t < 16; t++)
            v += M[s][t] * ((double)sG[t * 64 + c] / (double)srr[t]);
        g_PF2[b * 1024 + e] = (float)(v / (double)srr[s]);
    }
}

// ================= fold PF2 into conv2 proj-weights (fp16, [tap][64oc][16s]) =================
__global__ __launch_bounds__(256)
void w2eff_kernel(const float* __restrict__ Wc) {
    __shared__ float sPF[1024];
    int b = blockIdx.x, tid = threadIdx.x;
    for (int i = tid; i < 1024; i += 256) sPF[i] = g_PF2[b * 1024 + i];
    __syncthreads();
    for (int e = tid; e < 9216; e += 256) {
        int tap = e / 1024, r = e & 1023, o = r >> 4, s = r & 15;
        float v = 0.f;
#pragma unroll
        for (int c = 0; c < 64; c++)
            v += Wc[o * 1152 + (64 + c) * 9 + tap] * sPF[s * 64 + c];
        g_W2[(size_t)b * 9216 + (size_t)(tap * 1024 + o * 16 + s)] = __float2half(v);
    }
}

// ================= conv2: 64px strip x FULL 64oc, warp tile 32px x 64oc =================
// smem: Wx [0,73728), WU [73728,92160), slots [92160,155520) 6 x 10560
// slot layout: x [0,8448), U [8448,10560)
#define C2_WU 73728
#define C2_SLOT0 92160
#define C2_SLOTSZ 10560

__device__ __forceinline__ void c2_stage(u32 sb, int b, int x0, int ys, u32 slot, int tid) {
    bool yok = (unsigned)ys < 256u;
    int ysc = yok ? ys : 0;
    for (int i = tid; i < 660; i += 256) {
        if (i < 528) {
            int px = i >> 3, c8 = i & 7;
            int gx = x0 - 1 + px;
            bool ok = yok && (unsigned)gx < 256u;
            int gxc = ((unsigned)gx < 256u) ? gx : 0;
            const void* src = &g_in[PLANE(0, b) +
                                    (((size_t)(ysc * 256 + gxc)) << 6) + c8 * 8];
            u32 dst = sb + slot + (u32)(px * 128) +
                      (u32)((c8 * 16) ^ ((px & 7) << 4));
            cpa16(dst, src, ok);
        } else {
            int j = i - 528;
            int px = j >> 1, hf = j & 1;
            int gx = x0 - 1 + px;
            bool ok = yok && (unsigned)gx < 256u;
            int gxc = ((unsigned)gx < 256u) ? gx : 0;
            const void* src = &g_Uh[((size_t)b * HWN + (size_t)(ysc * 256 + gxc)) * 16 +
                                    hf * 8];
            u32 dst = sb + slot + 8448 + (u32)(px * 32 + hf * 16);
            cpa16(dst, src, ok);
        }
    }
}

__global__ __launch_bounds__(256)
void conv2_kernel(const float* __restrict__ x, float* __restrict__ out) {
    extern __shared__ __align__(16) unsigned char sm[];
    u32 sb = smem_u32(sm);
    int tid = threadIdx.x, lane = tid & 31, wid = tid >> 5;
    int b = blockIdx.z, y0 = blockIdx.y * 32, x0 = blockIdx.x * 64;

    // weights: x 72KB (all 64 oc) + U 18KB (this batch)
    for (int i = tid; i < 73728 / 16; i += 256)
        ((uint4*)sm)[i] = ((const uint4*)g_Wc2)[i];
    for (int i = tid; i < 18432 / 16; i += 256)
        ((uint4*)(sm + C2_WU))[i] =
            ((const uint4*)((const unsigned char*)g_W2 + (size_t)b * 18432))[i];

    int i8 = lane & 7, a_mh = (lane >> 3) & 1, a_kh = lane >> 4;
    int b_kh = (lane >> 3) & 1, b_nh = lane >> 4;
    int wm = wid & 1, ym = wid >> 1;                  // 2 warps/row, 4 rows/iter
    int apx = wm * 32 + a_mh * 8 + i8;
    u32 ocw[4], bxor[4];
#pragma unroll
    for (int j = 0; j < 4; j++) {
        ocw[j] = (u32)(b_nh * 8 + i8 + 16 * j);
        bxor[j] = (ocw[j] & 7) << 4;
    }
    int g = lane >> 2, t4 = lane & 3;

    for (int r = -1; r <= 4; r++)
        c2_stage(sb, b, x0, y0 + r, C2_SLOT0 + (u32)((r + 6) % 6) * C2_SLOTSZ, tid);
    CP_COMMIT();
    CP_WAIT0();
    __syncthreads();

    for (int t = 0; t < 8; t++) {
        int y = 4 * t + ym;
        int yy = y0 + y;

        float acc[2][8][4];
#pragma unroll
        for (int m = 0; m < 2; m++)
#pragma unroll
            for (int j = 0; j < 8; j++)
#pragma unroll
                for (int q = 0; q < 4; q++) acc[m][j][q] = 0.f;

#pragma unroll
        for (int ky = 0; ky < 3; ky++) {
            u32 sl = sb + C2_SLOT0 + (u32)(((y + ky - 1 + 6) % 6)) * C2_SLOTSZ;
#pragma unroll
            for (int kx = 0; kx < 3; kx++) {
                int tap = ky * 3 + kx;
                int p = apx + kx;
                u32 aoff = (u32)(p * 128);
                u32 asw = (u32)((p & 7) << 4);
                // x part: 4 k16 chunks
#pragma unroll
                for (int kc = 0; kc < 4; kc++) {
                    u32 kb = ((u32)(kc * 32 + a_kh * 16)) ^ asw;
                    u32 Ah0[4], Ah1[4];
                    ldm4(Ah0, sl + aoff + kb);
                    ldm4(Ah1, sl + aoff + 2048 + kb);
                    u32 bcol = (u32)(kc * 32 + b_kh * 16);
                    u32 BH[4][4];
#pragma unroll
                    for (int j = 0; j < 4; j++)
                        ldm4(BH[j], sb + (u32)(tap * 8192) + ocw[j] * 128 +
                                    (bcol ^ bxor[j]));
#pragma unroll
                    for (int j = 0; j < 4; j++)
#pragma unroll
                        for (int s = 0; s < 2; s++) {
                            mma16816(acc[0][2 * j + s], Ah0, BH[j] + 2 * s);
                            mma16816(acc[1][2 * j + s], Ah1, BH[j] + 2 * s);
                        }
                }
                // U part: single k16
                {
                    u32 uoff = sl + 8448 + (u32)(p * 32 + a_kh * 16);
                    u32 Ah0[4], Ah1[4];
                    ldm4(Ah0, uoff);
                    ldm4(Ah1, uoff + 512);
                    u32 BH[4][4];
#pragma unroll
                    for (int j = 0; j < 4; j++)
                        ldm4(BH[j], sb + C2_WU + (u32)(tap * 2048) + ocw[j] * 32 +
                                    (u32)(b_kh * 16));
#pragma unroll
                    for (int j = 0; j < 4; j++)
#pragma unroll
                        for (int s = 0; s < 2; s++) {
                            mma16816(acc[0][2 * j + s], Ah0, BH[j] + 2 * s);
                            mma16816(acc[1][2 * j + s], Ah1, BH[j] + 2 * s);
                        }
                }
            }
        }
        // writeout + residual: 32px x 64oc per warp
        size_t rowb0 = (size_t)yy * 256;
#pragma unroll
        for (int m = 0; m < 2; m++) {
            int px = x0 + wm * 32 + m * 16 + g;
            size_t rowb = rowb0 + px;
#pragma unroll
            for (int j4 = 0; j4 < 8; j4++) {
                int oc = (j4 >> 1) * 16 + (j4 & 1) * 8 + 2 * t4;
                size_t o0 = ((size_t)(b * 64 + oc) << 16) + rowb;
                size_t o1 = o0 + HWN;
                out[o0] = acc[m][j4][0] + x[o0];
                out[o1] = acc[m][j4][1] + x[o1];
                out[o0 + 8] = acc[m][j4][2] + x[o0 + 8];
                out[o1 + 8] = acc[m][j4][3] + x[o1 + 8];
            }
        }

        __syncthreads();
        if (t < 7) {
#pragma unroll
            for (int r = 5; r <= 8; r++)
                c2_stage(sb, b, x0, y0 + 4 * t + r,
                         C2_SLOT0 + (u32)((4 * t + r) % 6) * C2_SLOTSZ, tid);
            CP_COMMIT();
            CP_WAIT0();
            __syncthreads();
        }
    }
}

// ================= launch =================
extern "C" void kernel_launch(void* const* d_in, const int* in_sizes, int n_in,
                              void* d_out, int out_size) {
    const float* x      = (const float*)d_in[0];
    const float* bridge = (const float*)d_in[1];
    const float* Wsub   = (const float*)d_in[2];
    const float* Wcb    = (const float*)d_in[3];
    float* out = (float*)d_out;

    cudaFuncSetAttribute(conv1_kernel, cudaFuncAttributeMaxDynamicSharedMemorySize, 104448);
    cudaFuncSetAttribute(conv2_kernel, cudaFuncAttributeMaxDynamicSharedMemorySize, 155520);
    cudaFuncSetAttribute(reduce_kernel, cudaFuncAttributeMaxDynamicSharedMemorySize, RED_SM);

    prep_w_kernel<<<288, 256>>>(Wsub, Wcb);
    convert_kernel<<<dim3(1024, 2, 8), 256>>>(x, bridge);
    conv1_kernel<<<dim3(4, 16, 8), 128, 104448>>>();
    reduce_kernel<<<dim3(NCHUNK, BB), 256, RED_SM>>>();
    solve_kernel<<<BB, 256>>>();
    w2eff_kernel<<<BB, 256>>>(Wcb);
    conv2_kernel<<<dim3(4, 8, 8), 256, 155520>>>(x, out);
}

// round 16
// speedup vs baseline: 1.0038x; 1.0038x over previous
#include <cuda_runtime.h>
#include <cuda_fp16.h>
#include <cstdint>

#define BB 8
#define HWN 65536
#define NCHUNK 128
#define PART_STRIDE 1296

typedef uint32_t u32;

// ================= device scratch =================
// NHWC fp16 planes: [cg(0:x,1:bridge)][b][pixel][64ch]
__device__ __align__(16) __half g_in[(size_t)2 * 8 * HWN * 64];
#define PLANE(cg, b) (((size_t)((cg) * 8 + (b))) << 22)
__device__ __align__(16) __half g_Uh[(size_t)BB * HWN * 16];
__device__ __align__(16) float g_part[BB * NCHUNK * PART_STRIDE];
__device__ __align__(16) unsigned char g_Wc1[36864];
// conv2 x-weights fp16, ochalf-major: [oh][tap][32oc][64ic] = 73728 B
__device__ __align__(16) unsigned char g_Wc2[73728];
// conv2 U-weights fp16 per batch: [b][oh][tap][32oc][16s]
__device__ __align__(16) __half g_W2[(size_t)BB * 9216];

// ================= helpers =================
__device__ __forceinline__ u32 smem_u32(const void* p) {
    u32 a;
    asm("{ .reg .u64 t; cvta.to.shared.u64 t, %1; cvt.u32.u64 %0, t; }" : "=r"(a) : "l"(p));
    return a;
}
__device__ __forceinline__ void ldm4(u32* r, u32 a) {
    asm volatile("ldmatrix.sync.aligned.m8n8.x4.shared.b16 {%0,%1,%2,%3}, [%4];"
                 : "=r"(r[0]), "=r"(r[1]), "=r"(r[2]), "=r"(r[3]) : "r"(a));
}
__device__ __forceinline__ void ldm4t(u32* r, u32 a) {
    asm volatile("ldmatrix.sync.aligned.m8n8.x4.trans.shared.b16 {%0,%1,%2,%3}, [%4];"
                 : "=r"(r[0]), "=r"(r[1]), "=r"(r[2]), "=r"(r[3]) : "r"(a));
}
__device__ __forceinline__ void mma16816(float* c, const u32* a, const u32* b) {
    asm volatile("mma.sync.aligned.m16n8k16.row.col.f32.f16.f16.f32 "
                 "{%0,%1,%2,%3}, {%4,%5,%6,%7}, {%8,%9}, {%0,%1,%2,%3};"
                 : "+f"(c[0]), "+f"(c[1]), "+f"(c[2]), "+f"(c[3])
                 : "r"(a[0]), "r"(a[1]), "r"(a[2]), "r"(a[3]), "r"(b[0]), "r"(b[1]));
}
__device__ __forceinline__ void cpa16(u32 dst, const void* src, bool pred) {
    unsigned sz = pred ? 16u : 0u;
    asm volatile("cp.async.cg.shared.global [%0], [%1], 16, %2;"
                 :: "r"(dst), "l"(__cvta_generic_to_global(src)), "r"(sz));
}
#define CP_COMMIT() asm volatile("cp.async.commit_group;" ::: "memory")
#define CP_WAIT0()  asm volatile("cp.async.wait_group 0;" ::: "memory")

// ================= weight prep (single fp16) =================
__global__ void prep_w_kernel(const float* __restrict__ Ws, const float* __restrict__ Wc) {
    int id = blockIdx.x * 256 + threadIdx.x;
    if (id < 64 * 1152) {
        int oc = id / 1152, rem = id - oc * 1152, ic = rem / 9, tap = rem - ic * 9;
        if (ic < 64) {
            int oh = oc >> 5, ocl = oc & 31;
            u32 off = (u32)(oh * 36864 + tap * 4096 + ocl * 128) +
                      (u32)((ic * 2) ^ ((ocl & 7) << 4));
            *(__half*)(g_Wc2 + off) = __float2half(Wc[id]);
        }
    }
    if (id < 16 * 1152) {
        int oc = id / 1152, rem = id - oc * 1152, ic = rem / 9, tap = rem - ic * 9;
        u32 off = (u32)((tap * 16 + oc) * 256) + (u32)((ic * 2) ^ ((oc & 7) << 4));
        *(__half*)(g_Wc1 + off) = __float2half(Ws[id]);
    }
}

// ================= NCHW fp32 -> NHWC fp16 =================
__global__ __launch_bounds__(256)
void convert_kernel(const float* __restrict__ x, const float* __restrict__ bridge) {
    __shared__ float sT[64][68];
    int b = blockIdx.z, cg = blockIdx.y, pb = blockIdx.x;
    const float* src = cg ? bridge : x;
    int tid = threadIdx.x;
    int p0 = pb * 64;
    for (int i = tid; i < 64 * 64; i += 256) {
        int c = i >> 6, px = i & 63;
        sT[c][px] = src[((size_t)(b * 64 + c) << 16) + p0 + px];
    }
    __syncthreads();
    for (int i = tid; i < 512; i += 256) {
        int px = i >> 3, c8 = i & 7;
        __half hb[8];
#pragma unroll
        for (int j = 0; j < 8; j++)
            hb[j] = __float2half(sT[c8 * 8 + j][px]);
        size_t base = ((size_t)(p0 + px) << 6) + c8 * 8;
        *(uint4*)&g_in[PLANE(cg, b) + base] = *(uint4*)hb;
    }
}

// ================= conv1 (R14 config, minBlocks 2) =================
#define C1_SLOT0 36864
#define C1_SLOTSZ 16896

__device__ __forceinline__ void c1_stage(u32 sb, int b, int x0, int ys, u32 slot, int tid) {
    bool yok = (unsigned)ys < 256u;
    int ysc = yok ? ys : 0;
    for (int i = tid; i < 1056; i += 128) {
        int p = i / 528, j = i - p * 528;
        int px = j >> 3, c8 = j & 7;
        int gx = x0 - 1 + px;
        bool ok = yok && (unsigned)gx < 256u;
        int gxc = ((unsigned)gx < 256u) ? gx : 0;
        const void* src = &g_in[PLANE(p, b) +
                                (((size_t)(ysc * 256 + gxc)) << 6) + c8 * 8];
        u32 dst = sb + slot + (u32)(p * 8448 + px * 128) +
                  (u32)((c8 * 16) ^ ((px & 7) << 4));
        cpa16(dst, src, ok);
    }
}

__global__ __launch_bounds__(128, 2)
void conv1_kernel() {
    extern __shared__ __align__(16) unsigned char sm[];
    u32 sb = smem_u32(sm);
    int tid = threadIdx.x, lane = tid & 31, wid = tid >> 5;
    int b = blockIdx.z, y0 = blockIdx.y * 16, x0 = blockIdx.x * 64;

    for (int i = tid; i < 36864 / 16; i += 128)
        ((uint4*)sm)[i] = ((const uint4*)g_Wc1)[i];

    int i8 = lane & 7, a_mh = (lane >> 3) & 1, a_kh = lane >> 4;
    int b_kh = (lane >> 3) & 1, b_nh = lane >> 4;
    int wm = wid;
    int apx = wm * 16 + a_mh * 8 + i8;
    int ocw = b_nh * 8 + i8;
    u32 bRow = (u32)(ocw * 256), bx = (u32)((ocw & 7) << 4);
    int g = lane >> 2, t4 = lane & 3;

    c1_stage(sb, b, x0, y0 - 1, C1_SLOT0 + 3u * C1_SLOTSZ, tid);
    c1_stage(sb, b, x0, y0 + 0, C1_SLOT0 + 0u * C1_SLOTSZ, tid);
    c1_stage(sb, b, x0, y0 + 1, C1_SLOT0 + 1u * C1_SLOTSZ, tid);
    c1_stage(sb, b, x0, y0 + 2, C1_SLOT0 + 2u * C1_SLOTSZ, tid);
    CP_COMMIT();
    CP_WAIT0();
    __syncthreads();

    for (int t = 0; t < 8; t++) {
        float acc[2][2][4];
#pragma unroll
        for (int r = 0; r < 2; r++)
#pragma unroll
            for (int j = 0; j < 2; j++)
#pragma unroll
                for (int q = 0; q < 4; q++) acc[r][j][q] = 0.f;

#pragma unroll
        for (int ky = 0; ky < 3; ky++) {
            u32 sl0 = sb + C1_SLOT0 + (u32)(((2 * t + ky - 1) & 3)) * C1_SLOTSZ;
            u32 sl1 = sb + C1_SLOT0 + (u32)(((2 * t + ky) & 3)) * C1_SLOTSZ;
#pragma unroll
            for (int kx = 0; kx < 3; kx++) {
                int tap = ky * 3 + kx;
                int p = apx + kx;
                u32 aoff = (u32)(p * 128);
                u32 asw = (u32)((p & 7) << 4);
#pragma unroll
                for (int cg = 0; cg < 2; cg++) {
#pragma unroll
                    for (int kc = 0; kc < 4; kc++) {
                        u32 kb = ((u32)(kc * 32 + a_kh * 16)) ^ asw;
                        u32 Ah0[4], Ah1[4];
                        ldm4(Ah0, sl0 + (u32)(cg * 8448) + aoff + kb);
                        ldm4(Ah1, sl1 + (u32)(cg * 8448) + aoff + kb);
                        u32 ba = sb + (u32)(tap * 4096) + bRow +
                                 (((u32)(cg * 128 + kc * 32 + b_kh * 16)) ^ bx);
                        u32 BH[4];
                        ldm4(BH, ba);
#pragma unroll
                        for (int j = 0; j < 2; j++) {
                            mma16816(acc[0][j], Ah0, BH + 2 * j);
                            mma16816(acc[1][j], Ah1, BH + 2 * j);
                        }
                    }
                }
            }
        }
#pragma unroll
        for (int r = 0; r < 2; r++) {
            int yy = y0 + 2 * t + r;
            int px = x0 + wm * 16 + g;
            size_t rowb = (size_t)yy * 256 + px;
#pragma unroll
            for (int j = 0; j < 2; j++) {
                int oc = j * 8 + 2 * t4;
                size_t idx = ((size_t)b * HWN + rowb) * 16 + oc;
                __half2 hh;
                hh.x = __float2half(acc[r][j][0]);
                hh.y = __float2half(acc[r][j][1]);
                *(__half2*)&g_Uh[idx] = hh;
                hh.x = __float2half(acc[r][j][2]);
                hh.y = __float2half(acc[r][j][3]);
                *(__half2*)&g_Uh[idx + 128] = hh;
            }
        }

        __syncthreads();
        if (t < 7) {
            c1_stage(sb, b, x0, y0 + 2 * t + 3,
                     C1_SLOT0 + (u32)((2 * t + 3) & 3) * C1_SLOTSZ, tid);
            c1_stage(sb, b, x0, y0 + 2 * t + 4,
                     C1_SLOT0 + (u32)((2 * t + 4) & 3) * C1_SLOTSZ, tid);
            CP_COMMIT();
            CP_WAIT0();
            __syncthreads();
        }
    }
}

// ================= reduction via mma (unchanged from R14) =================
#define RED_SM 90112

__global__ __launch_bounds__(256)
void reduce_kernel() {
    extern __shared__ __align__(16) unsigned char rsm[];
    u32 sb = smem_u32(rsm);
    int b = blockIdx.y, ch = blockIdx.x;
    int tid = threadIdx.x, lane = tid & 31, w = tid >> 5;
    int n0 = ch * 512;

    for (int i = tid; i < 1024; i += 256) {
        int px = i >> 1, hf = i & 1;
        cpa16(sb + (u32)(px * 48 + hf * 16),
              &g_Uh[((size_t)b * HWN + n0 + px) * 16 + hf * 8], true);
    }
    for (int i = tid; i < 4096; i += 256) {
        int px = i >> 3, c8 = i & 7;
        cpa16(sb + 24576 + (u32)(px * 128) + (u32)((c8 * 16) ^ ((px & 7) << 4)),
              &g_in[PLANE(1, b) + (((size_t)(n0 + px)) << 6) + c8 * 8], true);
    }
    CP_COMMIT();
    CP_WAIT0();
    __syncthreads();

    float gacc[2][4];
    float Gacc[8][4];
#pragma unroll
    for (int j = 0; j < 2; j++)
#pragma unroll
        for (int q = 0; q < 4; q++) gacc[j][q] = 0.f;
#pragma unroll
    for (int j = 0; j < 8; j++)
#pragma unroll
        for (int q = 0; q < 4; q++) Gacc[j][q] = 0.f;

    u32 uLane = (u32)(((lane & 7) + ((lane >> 4) << 3)) * 48 + ((lane >> 3) & 1) * 16);
    u32 bLaneRow = (u32)(((lane & 7) + (((lane >> 3) & 1) << 3)) * 128);
    u32 bXor = (u32)((lane & 7) << 4);
    u32 cOff = (u32)((lane >> 4) * 16);

#pragma unroll
    for (int k = 0; k < 4; k++) {
        u32 kb = (u32)(w * 64 + k * 16);
        u32 Ar[4];
        ldm4t(Ar, sb + kb * 48 + uLane);
        u32 bg0[2] = {Ar[0], Ar[2]};
        u32 bg1[2] = {Ar[1], Ar[3]};
        mma16816(gacc[0], Ar, bg0);
        mma16816(gacc[1], Ar, bg1);
        u32 brow = sb + 24576 + kb * 128 + bLaneRow;
#pragma unroll
        for (int ng = 0; ng < 4; ng++) {
            u32 Br[4];
            ldm4t(Br, brow + (((u32)(ng * 32) + cOff) ^ bXor));
            mma16816(Gacc[2 * ng], Ar, Br);
            mma16816(Gacc[2 * ng + 1], Ar, Br + 2);
        }
    }

    float rl = 0.f;
    {
        int s = tid & 15, pb2 = (tid >> 4) * 32;
        for (int p2 = 0; p2 < 32; p2++) {
            __half u = *(const __half*)(rsm + (pb2 + p2) * 48 + s * 2);
            rl += fabsf(__half2float(u));
        }
    }
    __syncthreads();

    float* sp = (float*)rsm;
    int g = lane >> 2, t4 = lane & 3;
    int base = w * 1280;
#pragma unroll
    for (int h = 0; h < 2; h++) {
        int n = h * 8 + 2 * t4;
        sp[base + g * 16 + n] = gacc[h][0];
        sp[base + g * 16 + n + 1] = gacc[h][1];
        sp[base + (g + 8) * 16 + n] = gacc[h][2];
        sp[base + (g + 8) * 16 + n + 1] = gacc[h][3];
    }
#pragma unroll
    for (int set = 0; set < 8; set++) {
        int c = (set >> 1) * 16 + (set & 1) * 8 + 2 * t4;
        sp[base + 256 + g * 64 + c] = Gacc[set][0];
        sp[base + 256 + g * 64 + c + 1] = Gacc[set][1];
        sp[base + 256 + (g + 8) * 64 + c] = Gacc[set][2];
        sp[base + 256 + (g + 8) * 64 + c + 1] = Gacc[set][3];
    }
    sp[10240 + (tid & 15) * 16 + (tid >> 4)] = rl;
    __syncthreads();

    float* o = g_part + (size_t)(b * NCHUNK + ch) * PART_STRIDE;
    for (int i = tid; i < 1280; i += 256) {
        float a = 0.f;
#pragma unroll
        for (int w2 = 0; w2 < 8; w2++) a += sp[w2 * 1280 + i];
        o[i] = a;
    }
    if (tid < 16) {
        float a = 0.f;
#pragma unroll
        for (int j = 0; j < 16; j++) a += sp[10240 + tid * 16 + j];
        o[1280 + tid] = a;
    }
}

// ================= solve + fold PF2 into conv2 proj-weights (fused) =================
__global__ __launch_bounds__(256)
void solve_kernel(const float* __restrict__ Wc) {
    __shared__ float sGram[256];
    __shared__ float sG[1024];
    __shared__ float srr[16];
    __shared__ double A[16][17];
    __shared__ double M[16][17];
    __shared__ double spiv;
    __shared__ float sPF[1024];
    int b = blockIdx.x;
    int tid = threadIdx.x;
    const float* base = g_part + (size_t)b * NCHUNK * PART_STRIDE;
    {
        float a = 0.f;
        for (int ch = 0; ch < NCHUNK; ch++) a += base[ch * PART_STRIDE + tid];
        sGram[tid] = a;
    }
#pragma unroll
    for (int j = 0; j < 4; j++) {
        int e = tid + j * 256;
        float a = 0.f;
        for (int ch = 0; ch < NCHUNK; ch++) a += base[ch * PART_STRIDE + 256 + e];
        sG[e] = a;
    }
    if (tid < 16) {
        float a = 0.f;
        for (int ch = 0; ch < NCHUNK; ch++) a += base[ch * PART_STRIDE + 1280 + tid];
        srr[tid] = 1e-6f + a;
    }
    __syncthreads();
    {
        int i = tid >> 4, t = tid & 15;
        A[i][t] = (double)sGram[tid] / ((double)srr[i] * (double)srr[t]);
        M[i][t] = (i == t) ? 1.0 : 0.0;
    }
    __syncthreads();
    for (int k = 0; k < 16; k++) {
        if (tid == 0) spiv = 1.0 / A[k][k];
        __syncthreads();
        if (tid < 16) { A[k][tid] *= spiv; M[k][tid] *= spiv; }
        __syncthreads();
        int i = tid >> 4, t = tid & 15;
        double f = A[i][k];
        __syncthreads();
        if (i != k) { A[i][t] -= f * A[k][t]; M[i][t] -= f * M[k][t]; }
        __syncthreads();
    }
#pragma unroll
    for (int j = 0; j < 4; j++) {
        int e = tid + j * 256;
        int s = e >> 6, c = e & 63;
        double v = 0.0;
#pragma unroll
        for (int t = 0; t < 16; t++)
            v += M[s][t] * ((double)sG[t * 64 + c] / (double)srr[t]);
        sPF[s * 64 + c] = (float)(v / (double)srr[s]);
    }
    __syncthreads();
    // fold PF2 into conv2 proj-weights (fp16, ochalf-major)
    for (int e = tid; e < 9216; e += 256) {
        int tap = e / 1024, r = e & 1023, o = r >> 4, s = r & 15;
        float v = 0.f;
#pragma unroll
        for (int c = 0; c < 64; c++)
            v += Wc[o * 1152 + (64 + c) * 9 + tap] * sPF[s * 64 + c];
        int oh = o >> 5, ocl = o & 31;
        g_W2[(size_t)b * 9216 + (size_t)(oh * 4608 + tap * 512 + ocl * 16 + s)] =
            __float2half(v);
    }
}

// ================= conv2 (R14 config, minBlocks 2) =================
// slot layout: x [0,8448), U [8448,10560)
#define C2_WU 36864
#define C2_SLOT0 46080
#define C2_SLOTSZ 10560

__device__ __forceinline__ void c2_stage(u32 sb, int b, int x0, int ys, u32 slot, int tid) {
    bool yok = (unsigned)ys < 256u;
    int ysc = yok ? ys : 0;
    for (int i = tid; i < 660; i += 256) {
        if (i < 528) {
            int px = i >> 3, c8 = i & 7;
            int gx = x0 - 1 + px;
            bool ok = yok && (unsigned)gx < 256u;
            int gxc = ((unsigned)gx < 256u) ? gx : 0;
            const void* src = &g_in[PLANE(0, b) +
                                    (((size_t)(ysc * 256 + gxc)) << 6) + c8 * 8];
            u32 dst = sb + slot + (u32)(px * 128) +
                      (u32)((c8 * 16) ^ ((px & 7) << 4));
            cpa16(dst, src, ok);
        } else {
            int j = i - 528;
            int px = j >> 1, hf = j & 1;
            int gx = x0 - 1 + px;
            bool ok = yok && (unsigned)gx < 256u;
            int gxc = ((unsigned)gx < 256u) ? gx : 0;
            const void* src = &g_Uh[((size_t)b * HWN + (size_t)(ysc * 256 + gxc)) * 16 +
                                    hf * 8];
            u32 dst = sb + slot + 8448 + (u32)(px * 32 + hf * 16);
            cpa16(dst, src, ok);
        }
    }
}

__global__ __launch_bounds__(256, 2)
void conv2_kernel(const float* __restrict__ x, float* __restrict__ out) {
    extern __shared__ __align__(16) unsigned char sm[];
    u32 sb = smem_u32(sm);
    int tid = threadIdx.x, lane = tid & 31, wid = tid >> 5;
    int xs = blockIdx.x & 3, oh = blockIdx.x >> 2;
    int b = blockIdx.z, y0 = blockIdx.y * 32, x0 = xs * 64;

    for (int i = tid; i < 36864 / 16; i += 256)
        ((uint4*)sm)[i] = ((const uint4*)(g_Wc2 + oh * 36864))[i];
    for (int i = tid; i < 9216 / 16; i += 256)
        ((uint4*)(sm + C2_WU))[i] =
            ((const uint4*)((const unsigned char*)g_W2 + (size_t)b * 18432 + oh * 9216))[i];

    int i8 = lane & 7, a_mh = (lane >> 3) & 1, a_kh = lane >> 4;
    int b_kh = (lane >> 3) & 1, b_nh = lane >> 4;
    int wm = wid & 1, ym = wid >> 1;
    int apx = wm * 32 + a_mh * 8 + i8;
    u32 ocw[2];
    ocw[0] = (u32)(b_nh * 8 + i8);
    ocw[1] = ocw[0] + 16;
    int g = lane >> 2, t4 = lane & 3;

    for (int r = -1; r <= 4; r++)
        c2_stage(sb, b, x0, y0 + r, C2_SLOT0 + (u32)((r + 6) % 6) * C2_SLOTSZ, tid);
    CP_COMMIT();
    CP_WAIT0();
    __syncthreads();

    for (int t = 0; t < 8; t++) {
        int y = 4 * t + ym;
        int yy = y0 + y;

        float acc[2][4][4];
#pragma unroll
        for (int m = 0; m < 2; m++)
#pragma unroll
            for (int j = 0; j < 4; j++)
#pragma unroll
                for (int q = 0; q < 4; q++) acc[m][j][q] = 0.f;

#pragma unroll
        for (int ky = 0; ky < 3; ky++) {
            u32 sl = sb + C2_SLOT0 + (u32)(((y + ky - 1 + 6) % 6)) * C2_SLOTSZ;
#pragma unroll
            for (int kx = 0; kx < 3; kx++) {
                int tap = ky * 3 + kx;
                int p = apx + kx;
                u32 aoff = (u32)(p * 128);
                u32 asw = (u32)((p & 7) << 4);
#pragma unroll
                for (int kc = 0; kc < 4; kc++) {
                    u32 kb = ((u32)(kc * 32 + a_kh * 16)) ^ asw;
                    u32 Ah0[4], Ah1[4];
                    ldm4(Ah0, sl + aoff + kb);
                    ldm4(Ah1, sl + aoff + 2048 + kb);
                    u32 BH0[4], BH1[4];
                    u32 bcol = (u32)(kc * 32 + b_kh * 16);
                    u32 b0 = sb + (u32)(tap * 4096) + ocw[0] * 128 +
                             (bcol ^ ((ocw[0] & 7) << 4));
                    u32 b1 = sb + (u32)(tap * 4096) + ocw[1] * 128 +
                             (bcol ^ ((ocw[1] & 7) << 4));
                    ldm4(BH0, b0);
                    ldm4(BH1, b1);
#pragma unroll
                    for (int j = 0; j < 2; j++) {
                        mma16816(acc[0][j],     Ah0, BH0 + 2 * j);
                        mma16816(acc[0][2 + j], Ah0, BH1 + 2 * j);
                        mma16816(acc[1][j],     Ah1, BH0 + 2 * j);
                        mma16816(acc[1][2 + j], Ah1, BH1 + 2 * j);
                    }
                }
                {
                    u32 uoff = sl + 8448 + (u32)(p * 32 + a_kh * 16);
                    u32 Ah0[4], Ah1[4];
                    ldm4(Ah0, uoff);
                    ldm4(Ah1, uoff + 512);
                    u32 BH0[4], BH1[4];
                    u32 b0 = sb + C2_WU + (u32)(tap * 1024) + ocw[0] * 32 +
                             (u32)(b_kh * 16);
                    u32 b1 = sb + C2_WU + (u32)(tap * 1024) + ocw[1] * 32 +
                             (u32)(b_kh * 16);
                    ldm4(BH0, b0);
                    ldm4(BH1, b1);
#pragma unroll
                    for (int j = 0; j < 2; j++) {
                        mma16816(acc[0][j],     Ah0, BH0 + 2 * j);
                        mma16816(acc[0][2 + j], Ah0, BH1 + 2 * j);
                        mma16816(acc[1][j],     Ah1, BH0 + 2 * j);
                        mma16816(acc[1][2 + j], Ah1, BH1 + 2 * j);
                    }
                }
            }
        }
        size_t rowb0 = (size_t)yy * 256;
#pragma unroll
        for (int m = 0; m < 2; m++) {
            int px = x0 + wm * 32 + m * 16 + g;
            size_t rowb = rowb0 + px;
#pragma unroll
            for (int j4 = 0; j4 < 4; j4++) {
                int oc = oh * 32 + (j4 >> 1) * 16 + (j4 & 1) * 8 + 2 * t4;
                size_t o0 = ((size_t)(b * 64 + oc) << 16) + rowb;
                size_t o1 = o0 + HWN;
                out[o0] = acc[m][j4][0] + x[o0];
                out[o1] = acc[m][j4][1] + x[o1];
                out[o0 + 8] = acc[m][j4][2] + x[o0 + 8];
                out[o1 + 8] = acc[m][j4][3] + x[o1 + 8];
            }
        }

        __syncthreads();
        if (t < 7) {
#pragma unroll
            for (int r = 5; r <= 8; r++)
                c2_stage(sb, b, x0, y0 + 4 * t + r,
                         C2_SLOT0 + (u32)((4 * t + r) % 6) * C2_SLOTSZ, tid);
            CP_COMMIT();
            CP_WAIT0();
            __syncthreads();
        }
    }
}

// ================= launch =================
extern "C" void kernel_launch(void* const* d_in, const int* in_sizes, int n_in,
                              void* d_out, int out_size) {
    const float* x      = (const float*)d_in[0];
    const float* bridge = (const float*)d_in[1];
    const float* Wsub   = (const float*)d_in[2];
    const float* Wcb    = (const float*)d_in[3];
    float* out = (float*)d_out;

    cudaFuncSetAttribute(conv1_kernel, cudaFuncAttributeMaxDynamicSharedMemorySize, 104448);
    cudaFuncSetAttribute(conv2_kernel, cudaFuncAttributeMaxDynamicSharedMemorySize, 109440);
    cudaFuncSetAttribute(reduce_kernel, cudaFuncAttributeMaxDynamicSharedMemorySize, RED_SM);

    prep_w_kernel<<<288, 256>>>(Wsub, Wcb);
    convert_kernel<<<dim3(1024, 2, 8), 256>>>(x, bridge);
    conv1_kernel<<<dim3(4, 16, 8), 128, 104448>>>();
    reduce_kernel<<<dim3(NCHUNK, BB), 256, RED_SM>>>();
    solve_kernel<<<BB, 256>>>(Wcb);
    conv2_kernel<<<dim3(8, 8, 8), 256, 109440>>>(x, out);
}

// round 17
// speedup vs baseline: 1.0073x; 1.0034x over previous
#include <cuda_runtime.h>
#include <cuda_fp16.h>
#include <cstdint>

#define BB 8
#define HWN 65536
#define NCHUNK 128
#define PART_STRIDE 1296

typedef uint32_t u32;

// ================= device scratch =================
// NHWC fp16 planes: [cg(0:x,1:bridge)][b][pixel][64ch]
__device__ __align__(16) __half g_in[(size_t)2 * 8 * HWN * 64];
#define PLANE(cg, b) (((size_t)((cg) * 8 + (b))) << 22)
__device__ __align__(16) __half g_Uh[(size_t)BB * HWN * 16];
__device__ __align__(16) float g_part[BB * NCHUNK * PART_STRIDE];
__device__ __align__(16) unsigned char g_Wc1[36864];
// conv2 x-weights fp16, ochalf-major: [oh][tap][32oc][64ic] = 73728 B
__device__ __align__(16) unsigned char g_Wc2[73728];
// conv2 U-weights fp16 per batch: [b][oh][tap][32oc][16s]
__device__ __align__(16) __half g_W2[(size_t)BB * 9216];

// ================= helpers =================
__device__ __forceinline__ u32 smem_u32(const void* p) {
    u32 a;
    asm("{ .reg .u64 t; cvta.to.shared.u64 t, %1; cvt.u32.u64 %0, t; }" : "=r"(a) : "l"(p));
    return a;
}
__device__ __forceinline__ void ldm4(u32* r, u32 a) {
    asm volatile("ldmatrix.sync.aligned.m8n8.x4.shared.b16 {%0,%1,%2,%3}, [%4];"
                 : "=r"(r[0]), "=r"(r[1]), "=r"(r[2]), "=r"(r[3]) : "r"(a));
}
__device__ __forceinline__ void ldm4t(u32* r, u32 a) {
    asm volatile("ldmatrix.sync.aligned.m8n8.x4.trans.shared.b16 {%0,%1,%2,%3}, [%4];"
                 : "=r"(r[0]), "=r"(r[1]), "=r"(r[2]), "=r"(r[3]) : "r"(a));
}
__device__ __forceinline__ void mma16816(float* c, const u32* a, const u32* b) {
    asm volatile("mma.sync.aligned.m16n8k16.row.col.f32.f16.f16.f32 "
                 "{%0,%1,%2,%3}, {%4,%5,%6,%7}, {%8,%9}, {%0,%1,%2,%3};"
                 : "+f"(c[0]), "+f"(c[1]), "+f"(c[2]), "+f"(c[3])
                 : "r"(a[0]), "r"(a[1]), "r"(a[2]), "r"(a[3]), "r"(b[0]), "r"(b[1]));
}
__device__ __forceinline__ void cpa16(u32 dst, const void* src, bool pred) {
    unsigned sz = pred ? 16u : 0u;
    asm volatile("cp.async.cg.shared.global [%0], [%1], 16, %2;"
                 :: "r"(dst), "l"(__cvta_generic_to_global(src)), "r"(sz));
}
#define CP_COMMIT() asm volatile("cp.async.commit_group;" ::: "memory")
#define CP_WAIT0()  asm volatile("cp.async.wait_group 0;" ::: "memory")

// ================= weight prep (single fp16) =================
__global__ void prep_w_kernel(const float* __restrict__ Ws, const float* __restrict__ Wc) {
    int id = blockIdx.x * 256 + threadIdx.x;
    if (id < 64 * 1152) {
        int oc = id / 1152, rem = id - oc * 1152, ic = rem / 9, tap = rem - ic * 9;
        if (ic < 64) {
            int oh = oc >> 5, ocl = oc & 31;
            u32 off = (u32)(oh * 36864 + tap * 4096 + ocl * 128) +
                      (u32)((ic * 2) ^ ((ocl & 7) << 4));
            *(__half*)(g_Wc2 + off) = __float2half(Wc[id]);
        }
    }
    if (id < 16 * 1152) {
        int oc = id / 1152, rem = id - oc * 1152, ic = rem / 9, tap = rem - ic * 9;
        u32 off = (u32)((tap * 16 + oc) * 256) + (u32)((ic * 2) ^ ((oc & 7) << 4));
        *(__half*)(g_Wc1 + off) = __float2half(Ws[id]);
    }
}

// ================= NCHW fp32 -> NHWC fp16 =================
__global__ __launch_bounds__(256)
void convert_kernel(const float* __restrict__ x, const float* __restrict__ bridge) {
    __shared__ float sT[64][68];
    int b = blockIdx.z, cg = blockIdx.y, pb = blockIdx.x;
    const float* src = cg ? bridge : x;
    int tid = threadIdx.x;
    int p0 = pb * 64;
    for (int i = tid; i < 64 * 64; i += 256) {
        int c = i >> 6, px = i & 63;
        sT[c][px] = src[((size_t)(b * 64 + c) << 16) + p0 + px];
    }
    __syncthreads();
    for (int i = tid; i < 512; i += 256) {
        int px = i >> 3, c8 = i & 7;
        __half hb[8];
#pragma unroll
        for (int j = 0; j < 8; j++)
            hb[j] = __float2half(sT[c8 * 8 + j][px]);
        size_t base = ((size_t)(p0 + px) << 6) + c8 * 8;
        *(uint4*)&g_in[PLANE(cg, b) + base] = *(uint4*)hb;
    }
}

// ================= conv1 (R14 config) =================
#define C1_SLOT0 36864
#define C1_SLOTSZ 16896

__device__ __forceinline__ void c1_stage(u32 sb, int b, int x0, int ys, u32 slot, int tid) {
    bool yok = (unsigned)ys < 256u;
    int ysc = yok ? ys : 0;
    for (int i = tid; i < 1056; i += 128) {
        int p = i / 528, j = i - p * 528;
        int px = j >> 3, c8 = j & 7;
        int gx = x0 - 1 + px;
        bool ok = yok && (unsigned)gx < 256u;
        int gxc = ((unsigned)gx < 256u) ? gx : 0;
        const void* src = &g_in[PLANE(p, b) +
                                (((size_t)(ysc * 256 + gxc)) << 6) + c8 * 8];
        u32 dst = sb + slot + (u32)(p * 8448 + px * 128) +
                  (u32)((c8 * 16) ^ ((px & 7) << 4));
        cpa16(dst, src, ok);
    }
}

__global__ __launch_bounds__(128)
void conv1_kernel() {
    extern __shared__ __align__(16) unsigned char sm[];
    u32 sb = smem_u32(sm);
    int tid = threadIdx.x, lane = tid & 31, wid = tid >> 5;
    int b = blockIdx.z, y0 = blockIdx.y * 16, x0 = blockIdx.x * 64;

    for (int i = tid; i < 36864 / 16; i += 128)
        ((uint4*)sm)[i] = ((const uint4*)g_Wc1)[i];

    int i8 = lane & 7, a_mh = (lane >> 3) & 1, a_kh = lane >> 4;
    int b_kh = (lane >> 3) & 1, b_nh = lane >> 4;
    int wm = wid;
    int apx = wm * 16 + a_mh * 8 + i8;
    int ocw = b_nh * 8 + i8;
    u32 bRow = (u32)(ocw * 256), bx = (u32)((ocw & 7) << 4);
    int g = lane >> 2, t4 = lane & 3;

    c1_stage(sb, b, x0, y0 - 1, C1_SLOT0 + 3u * C1_SLOTSZ, tid);
    c1_stage(sb, b, x0, y0 + 0, C1_SLOT0 + 0u * C1_SLOTSZ, tid);
    c1_stage(sb, b, x0, y0 + 1, C1_SLOT0 + 1u * C1_SLOTSZ, tid);
    c1_stage(sb, b, x0, y0 + 2, C1_SLOT0 + 2u * C1_SLOTSZ, tid);
    CP_COMMIT();
    CP_WAIT0();
    __syncthreads();

    for (int t = 0; t < 8; t++) {
        float acc[2][2][4];
#pragma unroll
        for (int r = 0; r < 2; r++)
#pragma unroll
            for (int j = 0; j < 2; j++)
#pragma unroll
                for (int q = 0; q < 4; q++) acc[r][j][q] = 0.f;

#pragma unroll
        for (int ky = 0; ky < 3; ky++) {
            u32 sl0 = sb + C1_SLOT0 + (u32)(((2 * t + ky - 1) & 3)) * C1_SLOTSZ;
            u32 sl1 = sb + C1_SLOT0 + (u32)(((2 * t + ky) & 3)) * C1_SLOTSZ;
#pragma unroll
            for (int kx = 0; kx < 3; kx++) {
                int tap = ky * 3 + kx;
                int p = apx + kx;
                u32 aoff = (u32)(p * 128);
                u32 asw = (u32)((p & 7) << 4);
#pragma unroll
                for (int cg = 0; cg < 2; cg++) {
#pragma unroll
                    for (int kc = 0; kc < 4; kc++) {
                        u32 kb = ((u32)(kc * 32 + a_kh * 16)) ^ asw;
                        u32 Ah0[4], Ah1[4];
                        ldm4(Ah0, sl0 + (u32)(cg * 8448) + aoff + kb);
                        ldm4(Ah1, sl1 + (u32)(cg * 8448) + aoff + kb);
                        u32 ba = sb + (u32)(tap * 4096) + bRow +
                                 (((u32)(cg * 128 + kc * 32 + b_kh * 16)) ^ bx);
                        u32 BH[4];
                        ldm4(BH, ba);
#pragma unroll
                        for (int j = 0; j < 2; j++) {
                            mma16816(acc[0][j], Ah0, BH + 2 * j);
                            mma16816(acc[1][j], Ah1, BH + 2 * j);
                        }
                    }
                }
            }
        }
#pragma unroll
        for (int r = 0; r < 2; r++) {
            int yy = y0 + 2 * t + r;
            int px = x0 + wm * 16 + g;
            size_t rowb = (size_t)yy * 256 + px;
#pragma unroll
            for (int j = 0; j < 2; j++) {
                int oc = j * 8 + 2 * t4;
                size_t idx = ((size_t)b * HWN + rowb) * 16 + oc;
                __half2 hh;
                hh.x = __float2half(acc[r][j][0]);
                hh.y = __float2half(acc[r][j][1]);
                *(__half2*)&g_Uh[idx] = hh;
                hh.x = __float2half(acc[r][j][2]);
                hh.y = __float2half(acc[r][j][3]);
                *(__half2*)&g_Uh[idx + 128] = hh;
            }
        }

        __syncthreads();
        if (t < 7) {
            c1_stage(sb, b, x0, y0 + 2 * t + 3,
                     C1_SLOT0 + (u32)((2 * t + 3) & 3) * C1_SLOTSZ, tid);
            c1_stage(sb, b, x0, y0 + 2 * t + 4,
                     C1_SLOT0 + (u32)((2 * t + 4) & 3) * C1_SLOTSZ, tid);
            CP_COMMIT();
            CP_WAIT0();
            __syncthreads();
        }
    }
}

// ================= reduction via mma (R14) =================
#define RED_SM 90112

__global__ __launch_bounds__(256)
void reduce_kernel() {
    extern __shared__ __align__(16) unsigned char rsm[];
    u32 sb = smem_u32(rsm);
    int b = blockIdx.y, ch = blockIdx.x;
    int tid = threadIdx.x, lane = tid & 31, w = tid >> 5;
    int n0 = ch * 512;

    for (int i = tid; i < 1024; i += 256) {
        int px = i >> 1, hf = i & 1;
        cpa16(sb + (u32)(px * 48 + hf * 16),
              &g_Uh[((size_t)b * HWN + n0 + px) * 16 + hf * 8], true);
    }
    for (int i = tid; i < 4096; i += 256) {
        int px = i >> 3, c8 = i & 7;
        cpa16(sb + 24576 + (u32)(px * 128) + (u32)((c8 * 16) ^ ((px & 7) << 4)),
              &g_in[PLANE(1, b) + (((size_t)(n0 + px)) << 6) + c8 * 8], true);
    }
    CP_COMMIT();
    CP_WAIT0();
    __syncthreads();

    float gacc[2][4];
    float Gacc[8][4];
#pragma unroll
    for (int j = 0; j < 2; j++)
#pragma unroll
        for (int q = 0; q < 4; q++) gacc[j][q] = 0.f;
#pragma unroll
    for (int j = 0; j < 8; j++)
#pragma unroll
        for (int q = 0; q < 4; q++) Gacc[j][q] = 0.f;

    u32 uLane = (u32)(((lane & 7) + ((lane >> 4) << 3)) * 48 + ((lane >> 3) & 1) * 16);
    u32 bLaneRow = (u32)(((lane & 7) + (((lane >> 3) & 1) << 3)) * 128);
    u32 bXor = (u32)((lane & 7) << 4);
    u32 cOff = (u32)((lane >> 4) * 16);

#pragma unroll
    for (int k = 0; k < 4; k++) {
        u32 kb = (u32)(w * 64 + k * 16);
        u32 Ar[4];
        ldm4t(Ar, sb + kb * 48 + uLane);
        u32 bg0[2] = {Ar[0], Ar[2]};
        u32 bg1[2] = {Ar[1], Ar[3]};
        mma16816(gacc[0], Ar, bg0);
        mma16816(gacc[1], Ar, bg1);
        u32 brow = sb + 24576 + kb * 128 + bLaneRow;
#pragma unroll
        for (int ng = 0; ng < 4; ng++) {
            u32 Br[4];
            ldm4t(Br, brow + (((u32)(ng * 32) + cOff) ^ bXor));
            mma16816(Gacc[2 * ng], Ar, Br);
            mma16816(Gacc[2 * ng + 1], Ar, Br + 2);
        }
    }

    float rl = 0.f;
    {
        int s = tid & 15, pb2 = (tid >> 4) * 32;
        for (int p2 = 0; p2 < 32; p2++) {
            __half u = *(const __half*)(rsm + (pb2 + p2) * 48 + s * 2);
            rl += fabsf(__half2float(u));
        }
    }
    __syncthreads();

    float* sp = (float*)rsm;
    int g = lane >> 2, t4 = lane & 3;
    int base = w * 1280;
#pragma unroll
    for (int h = 0; h < 2; h++) {
        int n = h * 8 + 2 * t4;
        sp[base + g * 16 + n] = gacc[h][0];
        sp[base + g * 16 + n + 1] = gacc[h][1];
        sp[base + (g + 8) * 16 + n] = gacc[h][2];
        sp[base + (g + 8) * 16 + n + 1] = gacc[h][3];
    }
#pragma unroll
    for (int set = 0; set < 8; set++) {
        int c = (set >> 1) * 16 + (set & 1) * 8 + 2 * t4;
        sp[base + 256 + g * 64 + c] = Gacc[set][0];
        sp[base + 256 + g * 64 + c + 1] = Gacc[set][1];
        sp[base + 256 + (g + 8) * 64 + c] = Gacc[set][2];
        sp[base + 256 + (g + 8) * 64 + c + 1] = Gacc[set][3];
    }
    sp[10240 + (tid & 15) * 16 + (tid >> 4)] = rl;
    __syncthreads();

    float* o = g_part + (size_t)(b * NCHUNK + ch) * PART_STRIDE;
    for (int i = tid; i < 1280; i += 256) {
        float a = 0.f;
#pragma unroll
        for (int w2 = 0; w2 < 8; w2++) a += sp[w2 * 1280 + i];
        o[i] = a;
    }
    if (tid < 16) {
        float a = 0.f;
#pragma unroll
        for (int j = 0; j < 16; j++) a += sp[10240 + tid * 16 + j];
        o[1280 + tid] = a;
    }
}

// ================= solve + fold PF2 into conv2 proj-weights (fused) =================
__global__ __launch_bounds__(256)
void solve_kernel(const float* __restrict__ Wc) {
    __shared__ float sGram[256];
    __shared__ float sG[1024];
    __shared__ float srr[16];
    __shared__ double A[16][17];
    __shared__ double M[16][17];
    __shared__ double spiv;
    __shared__ float sPF[1024];
    int b = blockIdx.x;
    int tid = threadIdx.x;
    const float* base = g_part + (size_t)b * NCHUNK * PART_STRIDE;
    {
        float a = 0.f;
        for (int ch = 0; ch < NCHUNK; ch++) a += base[ch * PART_STRIDE + tid];
        sGram[tid] = a;
    }
#pragma unroll
    for (int j = 0; j < 4; j++) {
        int e = tid + j * 256;
        float a = 0.f;
        for (int ch = 0; ch < NCHUNK; ch++) a += base[ch * PART_STRIDE + 256 + e];
        sG[e] = a;
    }
    if (tid < 16) {
        float a = 0.f;
        for (int ch = 0; ch < NCHUNK; ch++) a += base[ch * PART_STRIDE + 1280 + tid];
        srr[tid] = 1e-6f + a;
    }
    __syncthreads();
    {
        int i = tid >> 4, t = tid & 15;
        A[i][t] = (double)sGram[tid] / ((double)srr[i] * (double)srr[t]);
        M[i][t] = (i == t) ? 1.0 : 0.0;
    }
    __syncthreads();
    for (int k = 0; k < 16; k++) {
        if (tid == 0) spiv = 1.0 / A[k][k];
        __syncthreads();
        if (tid < 16) { A[k][tid] *= spiv; M[k][tid] *= spiv; }
        __syncthreads();
        int i = tid >> 4, t = tid & 15;
        double f = A[i][k];
        __syncthreads();
        if (i != k) { A[i][t] -= f * A[k][t]; M[i][t] -= f * M[k][t]; }
        __syncthreads();
    }
#pragma unroll
    for (int j = 0; j < 4; j++) {
        int e = tid + j * 256;
        int s = e >> 6, c = e & 63;
        double v = 0.0;
#pragma unroll
        for (int t = 0; t < 16; t++)
            v += M[s][t] * ((double)sG[t * 64 + c] / (double)srr[t]);
        sPF[s * 64 + c] = (float)(v / (double)srr[s]);
    }
    __syncthreads();
    for (int e = tid; e < 9216; e += 256) {
        int tap = e / 1024, r = e & 1023, o = r >> 4, s = r & 15;
        float v = 0.f;
#pragma unroll
        for (int c = 0; c < 64; c++)
            v += Wc[o * 1152 + (64 + c) * 9 + tap] * sPF[s * 64 + c];
        int oh = o >> 5, ocl = o & 31;
        g_W2[(size_t)b * 9216 + (size_t)(oh * 4608 + tap * 512 + ocl * 16 + s)] =
            __float2half(v);
    }
}

// ================= conv2 (R14 config) =================
// slot layout: x [0,8448), U [8448,10560)
#define C2_WU 36864
#define C2_SLOT0 46080
#define C2_SLOTSZ 10560

__device__ __forceinline__ void c2_stage(u32 sb, int b, int x0, int ys, u32 slot, int tid) {
    bool yok = (unsigned)ys < 256u;
    int ysc = yok ? ys : 0;
    for (int i = tid; i < 660; i += 256) {
        if (i < 528) {
            int px = i >> 3, c8 = i & 7;
            int gx = x0 - 1 + px;
            bool ok = yok && (unsigned)gx < 256u;
            int gxc = ((unsigned)gx < 256u) ? gx : 0;
            const void* src = &g_in[PLANE(0, b) +
                                    (((size_t)(ysc * 256 + gxc)) << 6) + c8 * 8];
            u32 dst = sb + slot + (u32)(px * 128) +
                      (u32)((c8 * 16) ^ ((px & 7) << 4));
            cpa16(dst, src, ok);
        } else {
            int j = i - 528;
            int px = j >> 1, hf = j & 1;
            int gx = x0 - 1 + px;
            bool ok = yok && (unsigned)gx < 256u;
            int gxc = ((unsigned)gx < 256u) ? gx : 0;
            const void* src = &g_Uh[((size_t)b * HWN + (size_t)(ysc * 256 + gxc)) * 16 +
                                    hf * 8];
            u32 dst = sb + slot + 8448 + (u32)(px * 32 + hf * 16);
            cpa16(dst, src, ok);
        }
    }
}

__global__ __launch_bounds__(256)
void conv2_kernel(const float* __restrict__ x, float* __restrict__ out) {
    extern __shared__ __align__(16) unsigned char sm[];
    u32 sb = smem_u32(sm);
    int tid = threadIdx.x, lane = tid & 31, wid = tid >> 5;
    int xs = blockIdx.x & 3, oh = blockIdx.x >> 2;
    int b = blockIdx.z, y0 = blockIdx.y * 32, x0 = xs * 64;

    for (int i = tid; i < 36864 / 16; i += 256)
        ((uint4*)sm)[i] = ((const uint4*)(g_Wc2 + oh * 36864))[i];
    for (int i = tid; i < 9216 / 16; i += 256)
        ((uint4*)(sm + C2_WU))[i] =
            ((const uint4*)((const unsigned char*)g_W2 + (size_t)b * 18432 + oh * 9216))[i];

    int i8 = lane & 7, a_mh = (lane >> 3) & 1, a_kh = lane >> 4;
    int b_kh = (lane >> 3) & 1, b_nh = lane >> 4;
    int wm = wid & 1, ym = wid >> 1;
    int apx = wm * 32 + a_mh * 8 + i8;
    u32 ocw[2];
    ocw[0] = (u32)(b_nh * 8 + i8);
    ocw[1] = ocw[0] + 16;
    int g = lane >> 2, t4 = lane & 3;

    for (int r = -1; r <= 4; r++)
        c2_stage(sb, b, x0, y0 + r, C2_SLOT0 + (u32)((r + 6) % 6) * C2_SLOTSZ, tid);
    CP_COMMIT();
    CP_WAIT0();
    __syncthreads();

    for (int t = 0; t < 8; t++) {
        int y = 4 * t + ym;
        int yy = y0 + y;

        float acc[2][4][4];
#pragma unroll
        for (int m = 0; m < 2; m++)
#pragma unroll
            for (int j = 0; j < 4; j++)
#pragma unroll
                for (int q = 0; q < 4; q++) acc[m][j][q] = 0.f;

#pragma unroll
        for (int ky = 0; ky < 3; ky++) {
            u32 sl = sb + C2_SLOT0 + (u32)(((y + ky - 1 + 6) % 6)) * C2_SLOTSZ;
#pragma unroll
            for (int kx = 0; kx < 3; kx++) {
                int tap = ky * 3 + kx;
                int p = apx + kx;
                u32 aoff = (u32)(p * 128);
                u32 asw = (u32)((p & 7) << 4);
#pragma unroll
                for (int kc = 0; kc < 4; kc++) {
                    u32 kb = ((u32)(kc * 32 + a_kh * 16)) ^ asw;
                    u32 Ah0[4], Ah1[4];
                    ldm4(Ah0, sl + aoff + kb);
                    ldm4(Ah1, sl + aoff + 2048 + kb);
                    u32 BH0[4], BH1[4];
                    u32 bcol = (u32)(kc * 32 + b_kh * 16);
                    u32 b0 = sb + (u32)(tap * 4096) + ocw[0] * 128 +
                             (bcol ^ ((ocw[0] & 7) << 4));
                    u32 b1 = sb + (u32)(tap * 4096) + ocw[1] * 128 +
                             (bcol ^ ((ocw[1] & 7) << 4));
                    ldm4(BH0, b0);
                    ldm4(BH1, b1);
#pragma unroll
                    for (int j = 0; j < 2; j++) {
                        mma16816(acc[0][j],     Ah0, BH0 + 2 * j);
                        mma16816(acc[0][2 + j], Ah0, BH1 + 2 * j);
                        mma16816(acc[1][j],     Ah1, BH0 + 2 * j);
                        mma16816(acc[1][2 + j], Ah1, BH1 + 2 * j);
                    }
                }
                {
                    u32 uoff = sl + 8448 + (u32)(p * 32 + a_kh * 16);
                    u32 Ah0[4], Ah1[4];
                    ldm4(Ah0, uoff);
                    ldm4(Ah1, uoff + 512);
                    u32 BH0[4], BH1[4];
                    u32 b0 = sb + C2_WU + (u32)(tap * 1024) + ocw[0] * 32 +
                             (u32)(b_kh * 16);
                    u32 b1 = sb + C2_WU + (u32)(tap * 1024) + ocw[1] * 32 +
                             (u32)(b_kh * 16);
                    ldm4(BH0, b0);
                    ldm4(BH1, b1);
#pragma unroll
                    for (int j = 0; j < 2; j++) {
                        mma16816(acc[0][j],     Ah0, BH0 + 2 * j);
                        mma16816(acc[0][2 + j], Ah0, BH1 + 2 * j);
                        mma16816(acc[1][j],     Ah1, BH0 + 2 * j);
                        mma16816(acc[1][2 + j], Ah1, BH1 + 2 * j);
                    }
                }
            }
        }
        size_t rowb0 = (size_t)yy * 256;
#pragma unroll
        for (int m = 0; m < 2; m++) {
            int px = x0 + wm * 32 + m * 16 + g;
            size_t rowb = rowb0 + px;
#pragma unroll
            for (int j4 = 0; j4 < 4; j4++) {
                int oc = oh * 32 + (j4 >> 1) * 16 + (j4 & 1) * 8 + 2 * t4;
                size_t o0 = ((size_t)(b * 64 + oc) << 16) + rowb;
                size_t o1 = o0 + HWN;
                out[o0] = acc[m][j4][0] + x[o0];
                out[o1] = acc[m][j4][1] + x[o1];
                out[o0 + 8] = acc[m][j4][2] + x[o0 + 8];
                out[o1 + 8] = acc[m][j4][3] + x[o1 + 8];
            }
        }

        __syncthreads();
        if (t < 7) {
#pragma unroll
            for (int r = 5; r <= 8; r++)
                c2_stage(sb, b, x0, y0 + 4 * t + r,
                         C2_SLOT0 + (u32)((4 * t + r) % 6) * C2_SLOTSZ, tid);
            CP_COMMIT();
            CP_WAIT0();
            __syncthreads();
        }
    }
}

// ================= launch =================
extern "C" void kernel_launch(void* const* d_in, const int* in_sizes, int n_in,
                              void* d_out, int out_size) {
    const float* x      = (const float*)d_in[0];
    const float* bridge = (const float*)d_in[1];
    const float* Wsub   = (const float*)d_in[2];
    const float* Wcb    = (const float*)d_in[3];
    float* out = (float*)d_out;

    cudaFuncSetAttribute(conv1_kernel, cudaFuncAttributeMaxDynamicSharedMemorySize, 104448);
    cudaFuncSetAttribute(conv2_kernel, cudaFuncAttributeMaxDynamicSharedMemorySize, 109440);
    cudaFuncSetAttribute(reduce_kernel, cudaFuncAttributeMaxDynamicSharedMemorySize, RED_SM);

    prep_w_kernel<<<288, 256>>>(Wsub, Wcb);
    convert_kernel<<<dim3(1024, 2, 8), 256>>>(x, bridge);
    conv1_kernel<<<dim3(4, 16, 8), 128, 104448>>>();
    reduce_kernel<<<dim3(NCHUNK, BB), 256, RED_SM>>>();
    solve_kernel<<<BB, 256>>>(Wcb);
    conv2_kernel<<<dim3(8, 8, 8), 256, 109440>>>(x, out);
}